// round 1
// baseline (speedup 1.0000x reference)
#include <cuda_runtime.h>

#define BB 64
#define SS 196
#define DD 64
#define HALFS 98
#define OO 10

// 6.4 MB transposed cores: coresT[s][r][l][i] = cores[s][l][r][i]  (float2 over i)
__device__ float2 g_coresT[SS * DD * DD];
__device__ float g_vecL[BB][DD];
__device__ float g_vecR[BB][DD];

// ---------------------------------------------------------------------------
// Kernel 1: per-s 64x64 float2 transpose (l <-> r), keeps i-pair packed.
// ---------------------------------------------------------------------------
__global__ __launch_bounds__(256) void transpose_kernel(const float2* __restrict__ cores)
{
    __shared__ float2 tile[64][65];
    const int s = blockIdx.x;
    const float2* src = cores + (size_t)s * 4096;
    float2* dst = g_coresT + (size_t)s * 4096;

    for (int idx = threadIdx.x; idx < 4096; idx += 256) {
        tile[idx >> 6][idx & 63] = src[idx];   // coalesced read
    }
    __syncthreads();
    for (int idx = threadIdx.x; idx < 4096; idx += 256) {
        int r = idx >> 6, l = idx & 63;
        dst[idx] = tile[l][r];                 // coalesced write
    }
}

// ---------------------------------------------------------------------------
// Kernel 2: 128 independent chains (64 batches x {left,right}), G=2 batches/CTA.
// CTA: blockIdx = half*32 + pair.  Threads: t = g*64 + n, g = l-half, n = output.
// Per step k:  acc[j][i] = sum_m lv[j][m] * c_i[m][n];  lv_new = x0*acc0 + x1*acc1.
// Core slab for step k+1 is register-double-buffered to hide L2 latency.
// ---------------------------------------------------------------------------
__global__ __launch_bounds__(128) void chain_kernel(const float* __restrict__ x,
                                                    const float2* __restrict__ cores)
{
    __shared__ float2 lvbuf[2][64];   // [buf][n] = (lv_b0[n], lv_b1[n])
    __shared__ float4 part[2][64];    // [g][n] = (a00,a01,a10,a11)
    __shared__ float2 xs[2][HALFS];   // [j][k] = x[bj][s(k)][0..1]

    const int t = threadIdx.x;
    const int n = t & 63;
    const int g = t >> 6;
    const int half = blockIdx.x >> 5;
    const int pair = blockIdx.x & 31;
    const int b0 = pair * 2, b1 = b0 + 1;

    // Stage x scalars in iteration order
    const float2* xf = (const float2*)x;  // [B][S] float2
    for (int k = t; k < HALFS; k += 128) {
        int s = half ? (SS - 1 - k) : k;
        xs[0][k] = xf[b0 * SS + s];
        xs[1][k] = xf[b1 * SS + s];
    }
    if (t < 64) lvbuf[0][t] = make_float2(t == 0 ? 1.f : 0.f, t == 0 ? 1.f : 0.f);

    const float2* base = half ? (const float2*)g_coresT : cores;
    const float2* p = base + (half ? (size_t)(SS - 1) * 4096 : 0) + g * 2048 + n;
    const long stride = half ? -4096L : 4096L;   // float2 units per step

    __syncthreads();

    float2 A[32], Bf[32];
#pragma unroll
    for (int m = 0; m < 32; m++) A[m] = __ldg(p + m * 64);
    p += stride;

    int cb = 0;

#define CHAIN_STEP(BUF, KK)                                                    \
    {                                                                          \
        float a00 = 0.f, a01 = 0.f, a10 = 0.f, a11 = 0.f;                      \
        const int l0 = g * 32;                                                 \
        _Pragma("unroll")                                                      \
        for (int m = 0; m < 32; m++) {                                         \
            float2 lv = lvbuf[cb][l0 + m];                                     \
            float2 c  = BUF[m];                                                \
            a00 = fmaf(lv.x, c.x, a00);                                        \
            a01 = fmaf(lv.x, c.y, a01);                                        \
            a10 = fmaf(lv.y, c.x, a10);                                        \
            a11 = fmaf(lv.y, c.y, a11);                                        \
        }                                                                      \
        part[g][n] = make_float4(a00, a01, a10, a11);                          \
        __syncthreads();                                                       \
        if (t < 64) {                                                          \
            float4 pa = part[0][n], pb = part[1][n];                           \
            float2 x0 = xs[0][(KK)], x1 = xs[1][(KK)];                         \
            float nb0 = fmaf(x0.x, pa.x + pb.x, x0.y * (pa.y + pb.y));         \
            float nb1 = fmaf(x1.x, pa.z + pb.z, x1.y * (pa.w + pb.w));         \
            lvbuf[cb ^ 1][n] = make_float2(nb0, nb1);                          \
        }                                                                      \
        __syncthreads();                                                       \
        cb ^= 1;                                                               \
    }

#pragma unroll 1
    for (int k = 0; k < HALFS; k += 2) {
        // prefetch slab k+1 into Bf (k+1 <= 97 always since HALFS even)
#pragma unroll
        for (int m = 0; m < 32; m++) Bf[m] = __ldg(p + m * 64);
        p += stride;

        CHAIN_STEP(A, k);

        if (k + 2 < HALFS) {
#pragma unroll
            for (int m = 0; m < 32; m++) A[m] = __ldg(p + m * 64);
            p += stride;
        }

        CHAIN_STEP(Bf, k + 1);
    }
#undef CHAIN_STEP

    // 98 steps (even) -> final vectors in lvbuf[0]
    if (t < 64) {
        float2 v = lvbuf[0][n];
        if (half == 0) { g_vecL[b0][n] = v.x; g_vecL[b1][n] = v.y; }
        else           { g_vecR[b0][n] = v.x; g_vecR[b1][n] = v.y; }
    }
}

// ---------------------------------------------------------------------------
// Kernel 3: out[b,o] = sum_{l,r} L[b,l] * oc[o,l,r] * R[b,r]
// ---------------------------------------------------------------------------
__global__ __launch_bounds__(64) void out_kernel(const float* __restrict__ oc,
                                                 float* __restrict__ out)
{
    const int b = blockIdx.x;
    const int r = threadIdx.x;
    __shared__ float Ls[64];
    __shared__ float red[2][OO];

    Ls[r] = g_vecL[b][r];
    const float R = g_vecR[b][r];
    __syncthreads();

    for (int o = 0; o < OO; o++) {
        float acc = 0.f;
        const float* m = oc + o * 4096 + r;
#pragma unroll 8
        for (int l = 0; l < 64; l++) acc = fmaf(Ls[l], m[l * 64], acc);
        acc *= R;
#pragma unroll
        for (int off = 16; off; off >>= 1)
            acc += __shfl_down_sync(0xffffffffu, acc, off);
        if ((r & 31) == 0) red[r >> 5][o] = acc;
    }
    __syncthreads();
    if (r < OO) out[b * OO + r] = red[0][r] + red[1][r];
}

// ---------------------------------------------------------------------------
extern "C" void kernel_launch(void* const* d_in, const int* in_sizes, int n_in,
                              void* d_out, int out_size)
{
    const float* x = nullptr;
    const float* cores = nullptr;
    const float* oc = nullptr;
    for (int i = 0; i < n_in; i++) {
        if (in_sizes[i] == BB * SS * 2)           x = (const float*)d_in[i];
        else if (in_sizes[i] == SS * DD * DD * 2) cores = (const float*)d_in[i];
        else if (in_sizes[i] == OO * DD * DD)     oc = (const float*)d_in[i];
    }

    transpose_kernel<<<SS, 256>>>((const float2*)cores);
    chain_kernel<<<64, 128>>>(x, (const float2*)cores);
    out_kernel<<<BB, 64>>>(oc, (float*)d_out);
}

// round 2
// speedup vs baseline: 2.0450x; 2.0450x over previous
#include <cuda_runtime.h>
#include <cstdint>

#define BB 64
#define SS 196
#define DD 64
#define HALFS 98
#define UNITS 49            // 2 steps per unit
#define OO 10
#define SLAB 4096           // float2 elements per 64x64 slab
#define SLAB_BYTES 32768

// 6.4 MB transposed cores: coresT[s][r][l] (float2 over i), 128B aligned for bulk copy
__device__ __align__(128) float2 g_coresT[SS * DD * DD];
__device__ float g_vecL[BB][DD];
__device__ float g_vecR[BB][DD];

// ---------------------------------------------------------------------------
// PTX helpers
// ---------------------------------------------------------------------------
__device__ __forceinline__ uint32_t smem_u32(const void* p) {
    uint32_t a;
    asm("{ .reg .u64 t; cvta.to.shared.u64 t, %1; cvt.u32.u64 %0, t; }"
        : "=r"(a) : "l"(p));
    return a;
}
__device__ __forceinline__ void mbar_init(uint32_t a, uint32_t cnt) {
    asm volatile("mbarrier.init.shared.b64 [%0], %1;" :: "r"(a), "r"(cnt) : "memory");
}
__device__ __forceinline__ void mbar_arrive(uint32_t a) {
    asm volatile("mbarrier.arrive.shared.b64 _, [%0];" :: "r"(a) : "memory");
}
__device__ __forceinline__ void mbar_expect_tx(uint32_t a, uint32_t bytes) {
    asm volatile("mbarrier.arrive.expect_tx.shared.b64 _, [%0], %1;"
                 :: "r"(a), "r"(bytes) : "memory");
}
__device__ __forceinline__ void mbar_wait(uint32_t a, uint32_t phase) {
    asm volatile(
        "{\n\t"
        ".reg .pred P;\n\t"
        "WAIT_%=:\n\t"
        "mbarrier.try_wait.parity.shared.b64 P, [%0], %1;\n\t"
        "@!P bra WAIT_%=;\n\t"
        "}"
        :: "r"(a), "r"(phase) : "memory");
}
__device__ __forceinline__ void bulk_g2s(uint32_t dst, const void* src,
                                         uint32_t bytes, uint32_t mbar) {
    asm volatile(
        "cp.async.bulk.shared::cluster.global.mbarrier::complete_tx::bytes "
        "[%0], [%1], %2, [%3];"
        :: "r"(dst), "l"(src), "r"(bytes), "r"(mbar) : "memory");
}

// ---------------------------------------------------------------------------
// Kernel 1: per-s transpose (l <-> r), float2 i-pair kept packed. 392 blocks.
// ---------------------------------------------------------------------------
__global__ __launch_bounds__(256) void transpose_kernel(const float2* __restrict__ cores)
{
    __shared__ float2 tile[32][65];
    const int s  = blockIdx.x >> 1;
    const int l0 = (blockIdx.x & 1) * 32;
    const float2* src = cores + (size_t)s * SLAB + (size_t)l0 * 64;
    float2* dst = g_coresT + (size_t)s * SLAB + l0;

    for (int idx = threadIdx.x; idx < 32 * 64; idx += 256) {
        tile[idx >> 6][idx & 63] = src[idx];            // coalesced read
    }
    __syncthreads();
    for (int idx = threadIdx.x; idx < 32 * 64; idx += 256) {
        int r = idx >> 5, j = idx & 31;
        dst[r * 64 + j] = tile[j][r];                   // 256B coalesced write
    }
}

// ---------------------------------------------------------------------------
// Kernel 2: 128 chains, 2 per CTA (batches b0,b0+1, one half each CTA).
// Thread = (chain j, output n) computes FULL 64-term dot product -> no reduce.
// C slabs staged to shared via cp.async.bulk 4-deep ring, paired mbarriers.
// Per chain-step: 1 named barrier (2 warps) only.
// ---------------------------------------------------------------------------
__global__ __launch_bounds__(128, 1) void chain_kernel(const float* __restrict__ x,
                                                       const float2* __restrict__ cores)
{
    extern __shared__ __align__(128) unsigned char dynsm[];
    float2* Cbuf = (float2*)dynsm;                                   // 4 * 32KB
    float (*lvb)[2][64] = (float (*)[2][64])(dynsm + 4 * SLAB_BYTES); // [chain][buf][n]
    float2* xsh = (float2*)(dynsm + 4 * SLAB_BYTES + 1024);           // [chain][HALFS]
    uint64_t* bars = (uint64_t*)(dynsm + 4 * SLAB_BYTES + 1024 + 2 * HALFS * 8);
    const uint32_t bbase = smem_u32(bars);   // +0/+8 full pair0/1, +16/+24 empty pair0/1
    const uint32_t cb0   = smem_u32(Cbuf);

    const int t = threadIdx.x;
    const int n = t & 63;
    const int chain = t >> 6;
    const int half = blockIdx.x >> 5;
    const int b0 = (blockIdx.x & 31) * 2;

    // stage x in iteration order
    const float2* xf = (const float2*)x;     // [B][S] float2
    for (int k = t; k < HALFS; k += 128) {
        int s = half ? (SS - 1 - k) : k;
        xsh[0 * HALFS + k] = xf[(b0 + 0) * SS + s];
        xsh[1 * HALFS + k] = xf[(b0 + 1) * SS + s];
    }
    if (t < 64) { lvb[0][0][t] = (t == 0) ? 1.f : 0.f; lvb[1][0][t] = (t == 0) ? 1.f : 0.f; }

    // slab source for step k
    const float2* base = half ? (const float2*)g_coresT : cores;
    const float2* s0 = base + (half ? (size_t)(SS - 1) * SLAB : 0);
    const long sstride = half ? -(long)SLAB : (long)SLAB;

    if (t == 0) {
        mbar_init(bbase + 0, 1);    // full pair 0
        mbar_init(bbase + 8, 1);    // full pair 1
        mbar_init(bbase + 16, 4);   // empty pair 0 (4 warps)
        mbar_init(bbase + 24, 4);   // empty pair 1
    }
    __syncthreads();

    if (t == 0) {   // prologue: fill units 0 and 1 (steps 0..3)
        mbar_expect_tx(bbase + 0, 2 * SLAB_BYTES);
        bulk_g2s(cb0 + 0 * SLAB_BYTES, s0 + 0 * sstride, SLAB_BYTES, bbase + 0);
        bulk_g2s(cb0 + 1 * SLAB_BYTES, s0 + 1 * sstride, SLAB_BYTES, bbase + 0);
        mbar_expect_tx(bbase + 8, 2 * SLAB_BYTES);
        bulk_g2s(cb0 + 2 * SLAB_BYTES, s0 + 2 * sstride, SLAB_BYTES, bbase + 8);
        bulk_g2s(cb0 + 3 * SLAB_BYTES, s0 + 3 * sstride, SLAB_BYTES, bbase + 8);
    }

    int cb = 0;
    const int barid = 1 + chain;

#pragma unroll 1
    for (int j = 0; j < UNITS; j++) {
        const int p = j & 1;
        const uint32_t ph = (j >> 1) & 1;
        mbar_wait(bbase + p * 8, ph);          // data for steps 2j, 2j+1 ready

#pragma unroll
        for (int sub = 0; sub < 2; sub++) {
            const int k = 2 * j + sub;
            const float2* Cs = Cbuf + (p * 2 + sub) * SLAB + n;
            const float4* lv4 = (const float4*)&lvb[chain][cb][0];
            const float2 xk = xsh[chain * HALFS + k];

            float ax0 = 0.f, ax1 = 0.f, ax2 = 0.f, ax3 = 0.f;
            float ay0 = 0.f, ay1 = 0.f, ay2 = 0.f, ay3 = 0.f;
#pragma unroll
            for (int m4 = 0; m4 < 16; m4++) {
                float4 l4 = lv4[m4];
                float2 c0 = Cs[(4 * m4 + 0) * 64];
                float2 c1 = Cs[(4 * m4 + 1) * 64];
                float2 c2 = Cs[(4 * m4 + 2) * 64];
                float2 c3 = Cs[(4 * m4 + 3) * 64];
                ax0 = fmaf(l4.x, c0.x, ax0);  ay0 = fmaf(l4.x, c0.y, ay0);
                ax1 = fmaf(l4.y, c1.x, ax1);  ay1 = fmaf(l4.y, c1.y, ay1);
                ax2 = fmaf(l4.z, c2.x, ax2);  ay2 = fmaf(l4.z, c2.y, ay2);
                ax3 = fmaf(l4.w, c3.x, ax3);  ay3 = fmaf(l4.w, c3.y, ay3);
            }
            float sx = (ax0 + ax1) + (ax2 + ax3);
            float sy = (ay0 + ay1) + (ay2 + ay3);
            lvb[chain][cb ^ 1][n] = fmaf(xk.x, sx, xk.y * sy);
            cb ^= 1;
            asm volatile("bar.sync %0, 64;" :: "r"(barid) : "memory");
        }

        // both slabs of pair p consumed by this warp
        if ((t & 31) == 0) mbar_arrive(bbase + 16 + p * 8);

        if (t == 0 && j + 2 < UNITS) {
            mbar_wait(bbase + 16 + p * 8, ph);   // all 4 warps done with pair p
            mbar_expect_tx(bbase + p * 8, 2 * SLAB_BYTES);
            const int k0 = 2 * (j + 2);
            bulk_g2s(cb0 + (p * 2 + 0) * SLAB_BYTES, s0 + (long)(k0 + 0) * sstride,
                     SLAB_BYTES, bbase + p * 8);
            bulk_g2s(cb0 + (p * 2 + 1) * SLAB_BYTES, s0 + (long)(k0 + 1) * sstride,
                     SLAB_BYTES, bbase + p * 8);
        }
    }

    // 98 steps (even) -> final vector in buffer 0; thread n wrote its own slot.
    if (t < 128) {
        float v = lvb[chain][0][n];
        int b = b0 + chain;
        if (half == 0) g_vecL[b][n] = v;
        else           g_vecR[b][n] = v;
    }
}

// ---------------------------------------------------------------------------
// Kernel 3: out[b,o] = sum_{l,r} L[b,l] * oc[o,l,r] * R[b,r]
// ---------------------------------------------------------------------------
__global__ __launch_bounds__(64) void out_kernel(const float* __restrict__ oc,
                                                 float* __restrict__ out)
{
    const int b = blockIdx.x;
    const int r = threadIdx.x;
    __shared__ float Ls[64];
    __shared__ float red[2][OO];

    Ls[r] = g_vecL[b][r];
    const float R = g_vecR[b][r];
    __syncthreads();

    for (int o = 0; o < OO; o++) {
        float acc = 0.f;
        const float* m = oc + o * 4096 + r;
#pragma unroll 8
        for (int l = 0; l < 64; l++) acc = fmaf(Ls[l], m[l * 64], acc);
        acc *= R;
#pragma unroll
        for (int off = 16; off; off >>= 1)
            acc += __shfl_down_sync(0xffffffffu, acc, off);
        if ((r & 31) == 0) red[r >> 5][o] = acc;
    }
    __syncthreads();
    if (r < OO) out[b * OO + r] = red[0][r] + red[1][r];
}

// ---------------------------------------------------------------------------
extern "C" void kernel_launch(void* const* d_in, const int* in_sizes, int n_in,
                              void* d_out, int out_size)
{
    const float* x = nullptr;
    const float* cores = nullptr;
    const float* oc = nullptr;
    for (int i = 0; i < n_in; i++) {
        if (in_sizes[i] == BB * SS * 2)           x = (const float*)d_in[i];
        else if (in_sizes[i] == SS * DD * DD * 2) cores = (const float*)d_in[i];
        else if (in_sizes[i] == OO * DD * DD)     oc = (const float*)d_in[i];
    }

    const int DYN_SMEM = 4 * SLAB_BYTES + 1024 + 2 * HALFS * 8 + 64;
    cudaFuncSetAttribute(chain_kernel, cudaFuncAttributeMaxDynamicSharedMemorySize, DYN_SMEM);

    transpose_kernel<<<2 * SS, 256>>>((const float2*)cores);
    chain_kernel<<<64, 128, DYN_SMEM>>>(x, (const float2*)cores);
    out_kernel<<<BB, 64>>>(oc, (float*)d_out);
}